// round 16
// baseline (speedup 1.0000x reference)
#include <cuda_runtime.h>
#include <cuda_bf16.h>
#include <cstdint>
#include <math.h>

// GMM score via HMMA (mma.sync bf16), symmetry 2-split GEMM, component-split warps.
//   G[n,(c,j)] = sum_k A_c[j,k] xh_k        (GEMM on xh only; B in hi+lo splits)
//   x^T A x    = sum_j (xh+2*xl)_j G_j  (+ xl^T A xl dropped, ~2^-18)
//   d[n,c]     = quad + sum_j (xh+xl)_j * (-2 b_c[j]) + k_c
//   score      = exp(sum_c w_c log d)
// CTA: 256 thr / 128 samples; warp = 32 rows x ONE component (par = wid&1).
// Even/odd-par warps share rows, split comps; la merged once at the end.
// B traffic per warp = 16KB/chunk (its comp only) -> smem pressure -25%.

#define ROWB    144           // bytes per smem row (72 bf16, 64 used) — conflict-free ldmatrix
#define XHI_B   18432         // 128 rows * 144
#define HALF_BB 18432
#define CHUNK_B 36864         // hi + lo image of one B chunk

__device__ __align__(16) unsigned char g_B[8][CHUNK_B];
__device__ __align__(16) float g_bm2[1024];   // -2 * b_c[j],  [c*64 + j]
__device__ float g_kc[16];

__device__ __forceinline__ uint32_t smem_u32(const void* p) {
    uint32_t a;
    asm("{ .reg .u64 t; cvta.to.shared.u64 t, %1; cvt.u32.u64 %0, t; }" : "=r"(a) : "l"(p));
    return a;
}
__device__ __forceinline__ uint32_t pk(__nv_bfloat16 a, __nv_bfloat16 b) {
    __nv_bfloat162 t(a, b);
    return *reinterpret_cast<uint32_t*>(&t);
}

#define HMMA(acc, a, b0, b1)                                                  \
    asm volatile("mma.sync.aligned.m16n8k16.row.col.f32.bf16.bf16.f32 "       \
        "{%0,%1,%2,%3},{%4,%5,%6,%7},{%8,%9},{%0,%1,%2,%3};"                  \
        : "+f"((acc)[0]), "+f"((acc)[1]), "+f"((acc)[2]), "+f"((acc)[3])      \
        : "r"((a)[0]), "r"((a)[1]), "r"((a)[2]), "r"((a)[3]), "r"(b0), "r"(b1))

// ---------------- precomp 1: pack B hi/lo + b vectors ----------------
__global__ void precomp1(const float* __restrict__ A, const float* __restrict__ Mn) {
    if (blockIdx.x < 128) {
        const int idx   = blockIdx.x * 256 + threadIdx.x;   // 0..32767
        const int chunk = idx >> 12;
        const int rem   = idx & 4095;
        const int row   = rem >> 5;     // chunk-local col (par*64 + j)
        const int kp    = rem & 31;
        const int comp  = chunk * 2 + (row >> 6);
        const int j     = row & 63;
        const float2 v = *(const float2*)(A + comp * 4096 + j * 64 + kp * 2);
        __nv_bfloat16 h0 = __float2bfloat16(v.x), h1 = __float2bfloat16(v.y);
        __nv_bfloat16 l0 = __float2bfloat16(v.x - __bfloat162float(h0));
        __nv_bfloat16 l1 = __float2bfloat16(v.y - __bfloat162float(h1));
        *(uint32_t*)(g_B[chunk] + row * ROWB + kp * 4)           = pk(h0, h1);
        *(uint32_t*)(g_B[chunk] + HALF_BB + row * ROWB + kp * 4) = pk(l0, l1);
    } else {
        // b_c[j] = A_c[j,:] . m_c
        const int bi = (blockIdx.x - 128) * 256 + threadIdx.x;  // 0..1023
        const int c = bi >> 6, j = bi & 63;
        const float4* Ar = (const float4*)(A + c * 4096 + j * 64);
        const float4* mr = (const float4*)(Mn + c * 64);
        float s0 = 0, s1 = 0, s2 = 0, s3 = 0;
        #pragma unroll
        for (int t = 0; t < 16; t++) {
            float4 a = Ar[t], m = mr[t];
            s0 = fmaf(a.x, m.x, s0); s1 = fmaf(a.y, m.y, s1);
            s2 = fmaf(a.z, m.z, s2); s3 = fmaf(a.w, m.w, s3);
        }
        g_bm2[bi] = -2.0f * ((s0 + s1) + (s2 + s3));
    }
}

// ---------------- precomp 2: k_c = m_c^T b_c ----------------
__global__ void precomp2(const float* __restrict__ Mn) {
    const int c = threadIdx.x;
    if (c < 16) {
        float acc = 0.0f;
        #pragma unroll
        for (int j = 0; j < 64; j++)
            acc = fmaf(Mn[c * 64 + j], -0.5f * g_bm2[c * 64 + j], acc);
        g_kc[c] = acc;
    }
}

// ---------------- main kernel ----------------
// smem: Xhi [0,18432) | 2 x B buf | bm2 4KB | w/kc 128B | labuf 512B
#define SM_B0  XHI_B                          // 18432
#define SM_BM  (XHI_B + 2 * CHUNK_B)          // 92160
#define SM_WKC (SM_BM + 4096)                 // 96256
#define SM_LB  (SM_WKC + 128)                 // 96384
#define SMEM_BYTES (SM_LB + 512)              // 96896

__global__ void __launch_bounds__(256, 2)
gmm_hmma_kernel(const float* __restrict__ X, const float* __restrict__ W,
                float* __restrict__ out, int N)
{
    extern __shared__ unsigned char smem[];
    const uint32_t sb = smem_u32(smem);
    const int tid  = threadIdx.x;
    const int wid  = tid >> 5;
    const int lane = tid & 31;
    const int rg   = wid >> 1;     // row-group 0..3 (32 rows each)
    const int par  = wid & 1;      // component parity
    const int base = blockIdx.x * 128;

    // prefetch B chunk 0
    {
        size_t gsrc = __cvta_generic_to_global(g_B[0]);
        const uint32_t dst = sb + SM_B0;
        #pragma unroll
        for (int i = 0; i < 9; i++) {
            int o = (i * 256 + tid) * 16;
            asm volatile("cp.async.cg.shared.global [%0], [%1], 16;"
                         :: "r"(dst + o), "l"(gsrc + o));
        }
        asm volatile("cp.async.commit_group;");
    }
    if (tid < 16) {
        *(float*)(smem + SM_WKC + 4 * tid)      = W[tid];
        *(float*)(smem + SM_WKC + 64 + 4 * tid) = g_kc[tid];
    }
    ((float4*)(smem + SM_BM))[tid] = ((const float4*)g_bm2)[tid];  // 4KB

    // stage Xhi: row = tid>>1, half = tid&1 covers 32 cols
    {
        const int row = tid >> 1, half = tid & 1;
        const float4* xg = (const float4*)(X + (size_t)(base + row) * 64 + half * 32);
        unsigned char* rp = smem + row * ROWB + half * 64;
        #pragma unroll
        for (int q = 0; q < 8; q++) {
            float4 v = xg[q];
            *(uint2*)(rp + q * 8) = make_uint2(
                pk(__float2bfloat16(v.x), __float2bfloat16(v.y)),
                pk(__float2bfloat16(v.z), __float2bfloat16(v.w)));
        }
    }

    const int r0g = rg * 32 + (lane >> 2);   // local row of this thread's quad (rh*8 step)
    const int jb  = 2 * (lane & 3);          // quad col offset

    // xl packed bf16 (exact residual) for 4 row-groups; xh comes from smem Xhi image
    uint32_t xlp[4][8];
    {
        #pragma unroll
        for (int rh = 0; rh < 4; rh++) {
            const float* xr = X + (size_t)(base + r0g + rh * 8) * 64 + jb;
            #pragma unroll
            for (int q = 0; q < 8; q++) {
                float2 v = *(const float2*)(xr + q * 8);
                float l0 = v.x - __bfloat162float(__float2bfloat16(v.x));
                float l1 = v.y - __bfloat162float(__float2bfloat16(v.y));
                xlp[rh][q] = pk(__float2bfloat16(l0), __float2bfloat16(l1));
            }
        }
    }
    __syncthreads();

    float la[4] = {0.f, 0.f, 0.f, 0.f};
    const int arow0 = rg * 32 + ((lane >> 3) & 1) * 8 + (lane & 7);
    const uint32_t acoff = (lane >> 4) * 16;

    for (int c = 0; c < 8; c++) {
        asm volatile("cp.async.wait_group 0;");
        __syncthreads();

        if (c + 1 < 8) {
            size_t gsrc = __cvta_generic_to_global(g_B[c + 1]);
            const uint32_t dst = sb + SM_B0 + ((c + 1) & 1) * CHUNK_B;
            #pragma unroll
            for (int i = 0; i < 9; i++) {
                int o = (i * 256 + tid) * 16;
                asm volatile("cp.async.cg.shared.global [%0], [%1], 16;"
                             :: "r"(dst + o), "l"(gsrc + o));
            }
            asm volatile("cp.async.commit_group;");
        }

        const int cc = 2 * c + par;
        // B base: this warp's comp occupies image rows [par*64, par*64+64)
        const uint32_t Bb = sb + SM_B0 + (c & 1) * CHUNK_B
                          + (par * 64 + (lane >> 4) * 8 + (lane & 7)) * ROWB
                          + ((lane >> 3) & 1) * 16;
        const float* bm = (const float*)(smem + SM_BM) + cc * 64;

        float p[4] = {0.f, 0.f, 0.f, 0.f};

        #pragma unroll
        for (int nh = 0; nh < 2; nh++) {           // 32-col halves of this comp
            float acc[2][4][4];
            #pragma unroll
            for (int mt = 0; mt < 2; mt++)
                #pragma unroll
                for (int nt = 0; nt < 4; nt++) {
                    acc[mt][nt][0] = 0.f; acc[mt][nt][1] = 0.f;
                    acc[mt][nt][2] = 0.f; acc[mt][nt][3] = 0.f;
                }

            #pragma unroll
            for (int s = 0; s < 4; s++) {
                // A-fragments streamed from smem (8 transient regs per mt)
                uint32_t A0[4], A1[4];
                {
                    uint32_t ah = sb + arow0 * ROWB + acoff + s * 32;
                    asm volatile("ldmatrix.sync.aligned.m8n8.x4.shared.b16 {%0,%1,%2,%3}, [%4];"
                        : "=r"(A0[0]), "=r"(A0[1]), "=r"(A0[2]), "=r"(A0[3]) : "r"(ah));
                    asm volatile("ldmatrix.sync.aligned.m8n8.x4.shared.b16 {%0,%1,%2,%3}, [%4];"
                        : "=r"(A1[0]), "=r"(A1[1]), "=r"(A1[2]), "=r"(A1[3])
                        : "r"(ah + 16 * ROWB));
                }
                #pragma unroll
                for (int ntp = 0; ntp < 2; ntp++) {
                    uint32_t bh0, bh1, bh2, bh3, bl0, bl1, bl2, bl3;
                    const uint32_t ab = Bb + (nh * 32 + ntp * 16) * ROWB + s * 32;
                    asm volatile("ldmatrix.sync.aligned.m8n8.x4.shared.b16 {%0,%1,%2,%3}, [%4];"
                                 : "=r"(bh0), "=r"(bh1), "=r"(bh2), "=r"(bh3) : "r"(ab));
                    asm volatile("ldmatrix.sync.aligned.m8n8.x4.shared.b16 {%0,%1,%2,%3}, [%4];"
                                 : "=r"(bl0), "=r"(bl1), "=r"(bl2), "=r"(bl3) : "r"(ab + HALF_BB));
                    HMMA(acc[0][2*ntp],   A0, bh0, bh1);
                    HMMA(acc[0][2*ntp+1], A0, bh2, bh3);
                    HMMA(acc[1][2*ntp],   A1, bh0, bh1);
                    HMMA(acc[1][2*ntp+1], A1, bh2, bh3);
                    HMMA(acc[0][2*ntp],   A0, bl0, bl1);
                    HMMA(acc[0][2*ntp+1], A0, bl2, bl3);
                    HMMA(acc[1][2*ntp],   A1, bl0, bl1);
                    HMMA(acc[1][2*ntp+1], A1, bl2, bl3);
                }
            }

            // fold this n-half into p: quad term (wx = xh + 2xl) + linear (x = xh + xl)
            #pragma unroll
            for (int il2 = 0; il2 < 4; il2++) {
                const int jp = nh * 32 + il2 * 8 + jb;            // even col of pair
                const float2 bp = *(const float2*)(bm + jp);      // broadcast across quads
                #pragma unroll
                for (int rh = 0; rh < 4; rh++) {
                    const int mt = rh >> 1;
                    const int eb = (rh & 1) * 2;
                    // xh pair from Xhi image (conflict-free u32)
                    uint32_t xh_u = *(const uint32_t*)(smem + (r0g + rh * 8) * ROWB + jp * 2);
                    __nv_bfloat162 xh2 = *reinterpret_cast<__nv_bfloat162*>(&xh_u);
                    __nv_bfloat162 xl2 = *reinterpret_cast<__nv_bfloat162*>(&xlp[rh][nh * 4 + il2]);
                    const float h0 = __bfloat162float(xh2.x), h1 = __bfloat162float(xh2.y);
                    const float l0 = __bfloat162float(xl2.x), l1 = __bfloat162float(xl2.y);
                    // linear: exact x
                    p[rh] = fmaf(h0 + l0, bp.x, p[rh]);
                    p[rh] = fmaf(h1 + l1, bp.y, p[rh]);
                    // quad: wx = xh + 2*xl
                    p[rh] = fmaf(fmaf(2.0f, l0, h0), acc[mt][il2][eb],     p[rh]);
                    p[rh] = fmaf(fmaf(2.0f, l1, h1), acc[mt][il2][eb + 1], p[rh]);
                }
            }
        }

        const float wc = *(float*)(smem + SM_WKC + 4 * cc);
        const float kc = *(float*)(smem + SM_WKC + 64 + 4 * cc);
        #pragma unroll
        for (int rh = 0; rh < 4; rh++) {
            float v = p[rh];
            v += __shfl_xor_sync(0xFFFFFFFFu, v, 1);
            v += __shfl_xor_sync(0xFFFFFFFFu, v, 2);
            la[rh] = fmaf(wc, __logf(v + kc), la[rh]);
        }
    }

    // merge odd-par la into even-par, then write out
    if (par == 1 && (lane & 3) == 0) {
        #pragma unroll
        for (int rh = 0; rh < 4; rh++)
            *(float*)(smem + SM_LB + (r0g + rh * 8) * 4) = la[rh];
    }
    __syncthreads();
    if (par == 0 && (lane & 3) == 0) {
        #pragma unroll
        for (int rh = 0; rh < 4; rh++) {
            float o = la[rh] + *(float*)(smem + SM_LB + (r0g + rh * 8) * 4);
            out[base + r0g + rh * 8] = __expf(o);
        }
    }
}

// ---------------- launch ----------------
extern "C" void kernel_launch(void* const* d_in, const int* in_sizes, int n_in,
                              void* d_out, int out_size)
{
    const float* X     = (const float*)d_in[0];   // [N, 64]
    const float* Ainv  = (const float*)d_in[1];   // [16, 64, 64]
    const float* Means = (const float*)d_in[2];   // [16, 64]
    const float* W     = (const float*)d_in[3];   // [16]
    float* out = (float*)d_out;

    const int N = in_sizes[0] / 64;

    cudaFuncSetAttribute(gmm_hmma_kernel, cudaFuncAttributeMaxDynamicSharedMemorySize, SMEM_BYTES);

    precomp1<<<132, 256>>>(Ainv, Means);
    precomp2<<<1, 32>>>(Means);
    gmm_hmma_kernel<<<N / 128, 256, SMEM_BYTES>>>(X, W, out, N);
}

// round 17
// speedup vs baseline: 1.2349x; 1.2349x over previous
#include <cuda_runtime.h>
#include <cuda_bf16.h>
#include <cstdint>
#include <math.h>

// GMM score via HMMA (mma.sync bf16), symmetry 2-split GEMM, 2 CTAs/SM.
//   G[n,(c,j)] = sum_k A_c[j,k] xh_k        (GEMM on xh only; B in hi+lo splits)
//   x^T A x    = sum_j (xh+2*xl)_j G_j  (+ xl^T A xl dropped, ~2^-18)
//   L[n,c]     = x.(-2 b_c) + k_c  -- computed ONCE per CTA by a tiny prologue
//                HMMA GEMM (xh*bmhi + xh*bmlo + xl*bmhi) into sL[128][16] smem.
//   d[n,c]     = quad + L[n,c];  score = exp(sum_c w_c log d)
// Main loop is the measured-best 186us structure (no in-loop linear work).

#define ROWB    144           // bytes per smem row (72 bf16, 64 used) — conflict-free ldmatrix
#define XHI_B   18432         // 128 rows * 144
#define HALF_BB 18432
#define CHUNK_B 36864         // hi + lo image of one B chunk

__device__ __align__(16) unsigned char g_B[8][CHUNK_B];
__device__ __align__(16) float g_bm2[1024];            // -2*b_c[j], [c*64+j] (for precomp2)
__device__ __align__(16) unsigned char g_bmi[4608];    // bm2 bf16 images: hi [0,2304), lo [2304,4608); row=c (144B), col=j
__device__ float g_kc[16];

__device__ __forceinline__ uint32_t smem_u32(const void* p) {
    uint32_t a;
    asm("{ .reg .u64 t; cvta.to.shared.u64 t, %1; cvt.u32.u64 %0, t; }" : "=r"(a) : "l"(p));
    return a;
}
__device__ __forceinline__ uint32_t pk(__nv_bfloat16 a, __nv_bfloat16 b) {
    __nv_bfloat162 t(a, b);
    return *reinterpret_cast<uint32_t*>(&t);
}

#define HMMA(acc, a, b0, b1)                                                  \
    asm volatile("mma.sync.aligned.m16n8k16.row.col.f32.bf16.bf16.f32 "       \
        "{%0,%1,%2,%3},{%4,%5,%6,%7},{%8,%9},{%0,%1,%2,%3};"                  \
        : "+f"((acc)[0]), "+f"((acc)[1]), "+f"((acc)[2]), "+f"((acc)[3])      \
        : "r"((a)[0]), "r"((a)[1]), "r"((a)[2]), "r"((a)[3]), "r"(b0), "r"(b1))

// ---------------- precomp 1: pack B hi/lo + b vectors (+ bm bf16 images) ----------------
__global__ void precomp1(const float* __restrict__ A, const float* __restrict__ Mn) {
    if (blockIdx.x < 128) {
        const int idx   = blockIdx.x * 256 + threadIdx.x;   // 0..32767
        const int chunk = idx >> 12;
        const int rem   = idx & 4095;
        const int row   = rem >> 5;
        const int kp    = rem & 31;
        const int comp  = chunk * 2 + (row >> 6);
        const int j     = row & 63;
        const float2 v = *(const float2*)(A + comp * 4096 + j * 64 + kp * 2);
        __nv_bfloat16 h0 = __float2bfloat16(v.x), h1 = __float2bfloat16(v.y);
        __nv_bfloat16 l0 = __float2bfloat16(v.x - __bfloat162float(h0));
        __nv_bfloat16 l1 = __float2bfloat16(v.y - __bfloat162float(h1));
        *(uint32_t*)(g_B[chunk] + row * ROWB + kp * 4)           = pk(h0, h1);
        *(uint32_t*)(g_B[chunk] + HALF_BB + row * ROWB + kp * 4) = pk(l0, l1);
    } else {
        // b_c[j] = A_c[j,:] . m_c ;  bm2 = -2*b  (fp32 + bf16 hi/lo image)
        const int bi = (blockIdx.x - 128) * 256 + threadIdx.x;  // 0..1023
        const int c = bi >> 6, j = bi & 63;
        const float4* Ar = (const float4*)(A + c * 4096 + j * 64);
        const float4* mr = (const float4*)(Mn + c * 64);
        float s0 = 0, s1 = 0, s2 = 0, s3 = 0;
        #pragma unroll
        for (int t = 0; t < 16; t++) {
            float4 a = Ar[t], m = mr[t];
            s0 = fmaf(a.x, m.x, s0); s1 = fmaf(a.y, m.y, s1);
            s2 = fmaf(a.z, m.z, s2); s3 = fmaf(a.w, m.w, s3);
        }
        const float v = -2.0f * ((s0 + s1) + (s2 + s3));
        g_bm2[bi] = v;
        __nv_bfloat16 h = __float2bfloat16(v);
        __nv_bfloat16 l = __float2bfloat16(v - __bfloat162float(h));
        *(__nv_bfloat16*)(g_bmi + c * 144 + j * 2)        = h;
        *(__nv_bfloat16*)(g_bmi + 2304 + c * 144 + j * 2) = l;
    }
}

// ---------------- precomp 2: k_c = m_c^T b_c ----------------
__global__ void precomp2(const float* __restrict__ Mn) {
    const int c = threadIdx.x;
    if (c < 16) {
        float acc = 0.0f;
        #pragma unroll
        for (int j = 0; j < 64; j++)
            acc = fmaf(Mn[c * 64 + j], -0.5f * g_bm2[c * 64 + j], acc);
        g_kc[c] = acc;
    }
}

// ---------------- main kernel ----------------
// smem: Xhi [0,18432) | B buf0 | B buf1 (Xlo overlay pre-loop) | w 64 | kc 64 | sL 8KB | bmi 4608
#define SM_B0   XHI_B                         // 18432
#define SM_B1   (XHI_B + CHUNK_B)             // 55296
#define SM_W    (XHI_B + 2 * CHUNK_B)         // 92160
#define SM_KC   (SM_W + 64)                   // 92224
#define SM_L    (SM_KC + 64)                  // 92288
#define SM_BMI  (SM_L + 8192)                 // 100480
#define SMEM_BYTES (SM_BMI + 4608)            // 105088

__global__ void __launch_bounds__(256, 2)
gmm_hmma_kernel(const float* __restrict__ X, const float* __restrict__ W,
                float* __restrict__ out, int N)
{
    extern __shared__ unsigned char smem[];
    const uint32_t sb = smem_u32(smem);
    const int tid  = threadIdx.x;
    const int wid  = tid >> 5;
    const int lane = tid & 31;
    const int base = blockIdx.x * 128;

    // prefetch B chunk 0 -> buf0 (buf1 holds Xlo until iter 0)
    {
        size_t gsrc = __cvta_generic_to_global(g_B[0]);
        const uint32_t dst = sb + SM_B0;
        #pragma unroll
        for (int i = 0; i < 9; i++) {
            int o = (i * 256 + tid) * 16;
            asm volatile("cp.async.cg.shared.global [%0], [%1], 16;"
                         :: "r"(dst + o), "l"(gsrc + o));
        }
        asm volatile("cp.async.commit_group;");
    }
    if (tid < 16) {
        *(float*)(smem + SM_W  + 4 * tid) = W[tid];
        *(float*)(smem + SM_KC + 4 * tid) = g_kc[tid];
    }
    // bmi images -> smem (4608 B = 288 float4)
    for (int i = tid; i < 288; i += 256)
        ((float4*)(smem + SM_BMI))[i] = ((const float4*)g_bmi)[i];

    // stage Xhi (+ Xlo into buf1 overlay): row = tid>>1, half = tid&1 covers 32 cols
    {
        const int row = tid >> 1, half = tid & 1;
        const float4* xg = (const float4*)(X + (size_t)(base + row) * 64 + half * 32);
        unsigned char* rp = smem + row * ROWB + half * 64;
        unsigned char* rl = smem + SM_B1 + row * ROWB + half * 64;
        #pragma unroll
        for (int q = 0; q < 8; q++) {
            float4 v = xg[q];
            __nv_bfloat16 h0 = __float2bfloat16(v.x), h1 = __float2bfloat16(v.y);
            __nv_bfloat16 h2 = __float2bfloat16(v.z), h3 = __float2bfloat16(v.w);
            __nv_bfloat16 l0 = __float2bfloat16(v.x - __bfloat162float(h0));
            __nv_bfloat16 l1 = __float2bfloat16(v.y - __bfloat162float(h1));
            __nv_bfloat16 l2 = __float2bfloat16(v.z - __bfloat162float(h2));
            __nv_bfloat16 l3 = __float2bfloat16(v.w - __bfloat162float(h3));
            *(uint2*)(rp + q * 8) = make_uint2(pk(h0, h1), pk(h2, h3));
            *(uint2*)(rl + q * 8) = make_uint2(pk(l0, l1), pk(l2, l3));
        }
    }

    const int r0g = wid * 16 + (lane >> 2);

    // quad weights straight from global X:  wx = xh + 2*xl  (186us variant)
    float wx[2][16];
    {
        #pragma unroll
        for (int rh = 0; rh < 2; rh++) {
            const float* xr = X + (size_t)(base + r0g + rh * 8) * 64 + 2 * (lane & 3);
            #pragma unroll
            for (int q = 0; q < 8; q++) {
                float2 v = *(const float2*)(xr + q * 8);
                __nv_bfloat16 h0 = __float2bfloat16(v.x), h1 = __float2bfloat16(v.y);
                wx[rh][2*q]   = __bfloat162float(h0) + 2.0f * (v.x - __bfloat162float(h0));
                wx[rh][2*q+1] = __bfloat162float(h1) + 2.0f * (v.y - __bfloat162float(h1));
            }
        }
    }
    __syncthreads();

    // A-fragments (Xhi, persistent)
    uint32_t Ahi[4][4];
    {
        const int arow = wid * 16 + ((lane >> 3) & 1) * 8 + (lane & 7);
        const uint32_t coff = (lane >> 4) * 16;
        #pragma unroll
        for (int s = 0; s < 4; s++) {
            uint32_t ah = sb + arow * ROWB + coff + s * 32;
            asm volatile("ldmatrix.sync.aligned.m8n8.x4.shared.b16 {%0,%1,%2,%3}, [%4];"
                : "=r"(Ahi[s][0]), "=r"(Ahi[s][1]), "=r"(Ahi[s][2]), "=r"(Ahi[s][3]) : "r"(ah));
        }
    }

    // ---- prologue L-GEMM: L = X.(-2b)^T + k  (all state transient) ----
    {
        float LA[4] = {0.f, 0.f, 0.f, 0.f};   // comps 0..7
        float LB[4] = {0.f, 0.f, 0.f, 0.f};   // comps 8..15
        const int arow = wid * 16 + ((lane >> 3) & 1) * 8 + (lane & 7);
        const uint32_t coff = (lane >> 4) * 16;
        const uint32_t bmb = sb + SM_BMI + ((lane >> 4) * 8 + (lane & 7)) * 144
                           + ((lane >> 3) & 1) * 16;
        #pragma unroll
        for (int s = 0; s < 4; s++) {
            uint32_t Alo[4];
            uint32_t al = sb + SM_B1 + arow * ROWB + coff + s * 32;
            asm volatile("ldmatrix.sync.aligned.m8n8.x4.shared.b16 {%0,%1,%2,%3}, [%4];"
                : "=r"(Alo[0]), "=r"(Alo[1]), "=r"(Alo[2]), "=r"(Alo[3]) : "r"(al));
            uint32_t h0, h1, h2, h3, l0, l1, l2, l3;
            asm volatile("ldmatrix.sync.aligned.m8n8.x4.shared.b16 {%0,%1,%2,%3}, [%4];"
                         : "=r"(h0), "=r"(h1), "=r"(h2), "=r"(h3) : "r"(bmb + s * 32));
            asm volatile("ldmatrix.sync.aligned.m8n8.x4.shared.b16 {%0,%1,%2,%3}, [%4];"
                         : "=r"(l0), "=r"(l1), "=r"(l2), "=r"(l3) : "r"(bmb + 2304 + s * 32));
            HMMA(LA, Ahi[s], h0, h1);  HMMA(LB, Ahi[s], h2, h3);
            HMMA(LA, Ahi[s], l0, l1);  HMMA(LB, Ahi[s], l2, l3);
            HMMA(LA, Alo,    h0, h1);  HMMA(LB, Alo,    h2, h3);
        }
        // store sL[row][comp] = L + k_c
        #pragma unroll
        for (int nt = 0; nt < 2; nt++) {
            const float* Lc = nt ? LB : LA;
            #pragma unroll
            for (int e = 0; e < 4; e++) {
                const int row  = r0g + (e >> 1) * 8;
                const int comp = nt * 8 + 2 * (lane & 3) + (e & 1);
                const float kcv = *(const float*)(smem + SM_KC + 4 * comp);
                *(float*)(smem + SM_L + (row * 16 + comp) * 4) = Lc[e] + kcv;
            }
        }
    }
    __syncthreads();   // sL done; Xlo (buf1) no longer needed

    float la0 = 0.0f, la1 = 0.0f;

    for (int c = 0; c < 8; c++) {
        asm volatile("cp.async.wait_group 0;");
        __syncthreads();

        if (c + 1 < 8) {
            size_t gsrc = __cvta_generic_to_global(g_B[c + 1]);
            const uint32_t dst = sb + SM_B0 + ((c + 1) & 1) * CHUNK_B;
            #pragma unroll
            for (int i = 0; i < 9; i++) {
                int o = (i * 256 + tid) * 16;
                asm volatile("cp.async.cg.shared.global [%0], [%1], 16;"
                             :: "r"(dst + o), "l"(gsrc + o));
            }
            asm volatile("cp.async.commit_group;");
        }

        // L values for this chunk's 2 comps, 2 row-groups (broadcast within quad)
        const float2 L0 = *(const float2*)(smem + SM_L + (r0g * 16 + 2 * c) * 4);
        const float2 L1 = *(const float2*)(smem + SM_L + ((r0g + 8) * 16 + 2 * c) * 4);

        const uint32_t Bb = sb + SM_B0 + (c & 1) * CHUNK_B
                          + ((lane >> 4) * 8 + (lane & 7)) * ROWB + ((lane >> 3) & 1) * 16;

        #pragma unroll
        for (int half = 0; half < 2; half++) {
            const int cc = 2 * c + half;
            float acc[8][4];
            #pragma unroll
            for (int t = 0; t < 8; t++) { acc[t][0]=0.f; acc[t][1]=0.f; acc[t][2]=0.f; acc[t][3]=0.f; }

            #pragma unroll
            for (int t2 = 0; t2 < 4; t2++) {
                #pragma unroll
                for (int s = 0; s < 4; s++) {
                    uint32_t bh0, bh1, bh2, bh3, bl0, bl1, bl2, bl3;
                    const uint32_t ab = Bb + (half * 64 + t2 * 16) * ROWB + s * 32;
                    asm volatile("ldmatrix.sync.aligned.m8n8.x4.shared.b16 {%0,%1,%2,%3}, [%4];"
                                 : "=r"(bh0), "=r"(bh1), "=r"(bh2), "=r"(bh3) : "r"(ab));
                    asm volatile("ldmatrix.sync.aligned.m8n8.x4.shared.b16 {%0,%1,%2,%3}, [%4];"
                                 : "=r"(bl0), "=r"(bl1), "=r"(bl2), "=r"(bl3) : "r"(ab + HALF_BB));
                    HMMA(acc[2*t2],   Ahi[s], bh0, bh1);
                    HMMA(acc[2*t2+1], Ahi[s], bh2, bh3);
                    HMMA(acc[2*t2],   Ahi[s], bl0, bl1);
                    HMMA(acc[2*t2+1], Ahi[s], bl2, bl3);
                }
            }

            // epilogue: p = sum_j wx_j G_j; d = p + L
            float p0 = 0.f, p1 = 0.f;
            #pragma unroll
            for (int t = 0; t < 8; t++) {
                p0 = fmaf(wx[0][t*2],   acc[t][0], p0);
                p0 = fmaf(wx[0][t*2+1], acc[t][1], p0);
                p1 = fmaf(wx[1][t*2],   acc[t][2], p1);
                p1 = fmaf(wx[1][t*2+1], acc[t][3], p1);
            }
            p0 += __shfl_xor_sync(0xFFFFFFFFu, p0, 1); p0 += __shfl_xor_sync(0xFFFFFFFFu, p0, 2);
            p1 += __shfl_xor_sync(0xFFFFFFFFu, p1, 1); p1 += __shfl_xor_sync(0xFFFFFFFFu, p1, 2);

            const float wc = *(float*)(smem + SM_W + 4 * cc);
            la0 = fmaf(wc, __logf(p0 + (half ? L0.y : L0.x)), la0);
            la1 = fmaf(wc, __logf(p1 + (half ? L1.y : L1.x)), la1);
        }
    }

    if ((lane & 3) == 0) {
        out[base + r0g]     = __expf(la0);
        out[base + r0g + 8] = __expf(la1);
    }
}

// ---------------- launch ----------------
extern "C" void kernel_launch(void* const* d_in, const int* in_sizes, int n_in,
                              void* d_out, int out_size)
{
    const float* X     = (const float*)d_in[0];   // [N, 64]
    const float* Ainv  = (const float*)d_in[1];   // [16, 64, 64]
    const float* Means = (const float*)d_in[2];   // [16, 64]
    const float* W     = (const float*)d_in[3];   // [16]
    float* out = (float*)d_out;

    const int N = in_sizes[0] / 64;

    cudaFuncSetAttribute(gmm_hmma_kernel, cudaFuncAttributeMaxDynamicSharedMemorySize, SMEM_BYTES);

    precomp1<<<132, 256>>>(Ainv, Means);
    precomp2<<<1, 32>>>(Means);
    gmm_hmma_kernel<<<N / 128, 256, SMEM_BYTES>>>(X, W, out, N);
}